// round 7
// baseline (speedup 1.0000x reference)
#include <cuda_runtime.h>
#include <cuda_fp16.h>
#include <cstdint>

// ---------------------------------------------------------------------------
// SimpleGCN on B200, round 7:
//   gather: warp-per-node (4 edge-groups x 8 col-groups), fp16 h, shfl reduce
//           -> 4x memory-level parallelism vs round 6, chain length deg/4.
//   gemm:   packed fma.rn.f32x2 (2 FMA lanes per issue) -> halves FFMA issue.
//   Accumulation/norms/outputs fp32; h fp16 (rel_err ~7e-5 validated R6).
// ---------------------------------------------------------------------------

#define MAXN (1 << 17)
#define MAXE (1 << 21)
#define FDIM 64

struct alignas(16) H8 { __half2 a, b, c, d; };   // 8 halves = 16 B

__device__ __half g_h[(size_t)MAXN * FDIM];
__device__ float  g_acc[(size_t)MAXN * FDIM];
__device__ float  g_dinv[MAXN];
__device__ int    g_cnt[MAXN];
__device__ int    g_row[MAXN];
__device__ int    g_cur[MAXN];
__device__ int    g_bsum[256];
__device__ int2   g_edata[MAXE];
__device__ int    g_is64;

// --- packed f32x2 helpers (Blackwell; ptxas won't auto-fuse) ---
__device__ __forceinline__ unsigned long long ffma2(
    unsigned long long a, unsigned long long b, unsigned long long c) {
    unsigned long long d;
    asm("fma.rn.f32x2 %0, %1, %2, %3;" : "=l"(d) : "l"(a), "l"(b), "l"(c));
    return d;
}
__device__ __forceinline__ unsigned long long pack2(float x) {
    unsigned long long p;
    asm("mov.b64 %0, {%1, %1};" : "=l"(p) : "f"(x));
    return p;
}
__device__ __forceinline__ float2 unpack2(unsigned long long p) {
    float lo, hi;
    asm("mov.b64 {%0, %1}, %2;" : "=f"(lo), "=f"(hi) : "l"(p));
    return make_float2(lo, hi);
}

// --- dtype detection: int64 LE with small values has zero odd 32-bit words
__global__ void k_detect(const unsigned int* __restrict__ w, long long nwords) {
    __shared__ int cnt;
    if (threadIdx.x == 0) cnt = 0;
    __syncthreads();
    int zeros = 0;
    for (long long i = threadIdx.x; i < 2048 && i < nwords; i += blockDim.x)
        if ((i & 1) && w[i] == 0u) zeros++;
    atomicAdd(&cnt, zeros);
    __syncthreads();
    if (threadIdx.x == 0) g_is64 = (cnt > 512) ? 1 : 0;
}

__device__ __forceinline__ int load_idx(const void* e, long long pos) {
    if (g_is64) return (int)((const long long*)e)[pos];
    return ((const int*)e)[pos];
}

__global__ void k_zero2(int n) {
    int i = blockIdx.x * blockDim.x + threadIdx.x;
    if (i < n) { g_cnt[i] = 0; g_cur[i] = 0; }
}

__global__ void k_deg(const void* __restrict__ e, long long E) {
    long long i = (long long)blockIdx.x * blockDim.x + threadIdx.x;
    if (i >= E) return;
    atomicAdd(&g_cnt[load_idx(e, E + i)], 1);
}

__global__ void k_dinv(int n) {
    int i = blockIdx.x * blockDim.x + threadIdx.x;
    if (i < n) g_dinv[i] = rsqrtf((float)(1 + g_cnt[i]));
}

// --- exclusive scan of g_cnt -> g_row
__global__ void k_scan1(int n) {
    __shared__ int sh[1024];
    int i = blockIdx.x * 1024 + threadIdx.x;
    int v = (i < n) ? g_cnt[i] : 0;
    sh[threadIdx.x] = v;
    __syncthreads();
#pragma unroll
    for (int off = 1; off < 1024; off <<= 1) {
        int t = (threadIdx.x >= off) ? sh[threadIdx.x - off] : 0;
        __syncthreads();
        sh[threadIdx.x] += t;
        __syncthreads();
    }
    if (i < n) g_row[i] = sh[threadIdx.x] - v;
    if (threadIdx.x == 1023) g_bsum[blockIdx.x] = sh[1023];
}

__global__ void k_scan2(int nb) {
    __shared__ int sh[256];
    int v = (threadIdx.x < nb) ? g_bsum[threadIdx.x] : 0;
    sh[threadIdx.x] = v;
    __syncthreads();
#pragma unroll
    for (int off = 1; off < 256; off <<= 1) {
        int t = (threadIdx.x >= off) ? sh[threadIdx.x - off] : 0;
        __syncthreads();
        sh[threadIdx.x] += t;
        __syncthreads();
    }
    if (threadIdx.x < nb) g_bsum[threadIdx.x] = sh[threadIdx.x] - v;
}

__global__ void k_scan3(int n) {
    int i = blockIdx.x * 1024 + threadIdx.x;
    if (i < n) g_row[i] += g_bsum[blockIdx.x];
}

__global__ void k_fill(const void* __restrict__ e, long long E) {
    long long i = (long long)blockIdx.x * blockDim.x + threadIdx.x;
    if (i >= E) return;
    int s, d;
    if (g_is64) {
        const long long* p = (const long long*)e;
        s = (int)p[i]; d = (int)p[E + i];
    } else {
        const int* p = (const int*)e;
        s = p[i]; d = p[E + i];
    }
    int pos = g_row[d] + atomicAdd(&g_cur[d], 1);
    g_edata[pos] = make_int2(s, __float_as_int(g_dinv[s] * g_dinv[d]));
}

// --- GEMM: h = act(in) @ W via packed f32x2 FMA; fp16 epilogue.
template <int LRELU>
__global__ void __launch_bounds__(128)
k_gemm(const float* __restrict__ in, const float* __restrict__ W,
       __half* __restrict__ h, int n) {
    __shared__ float Ws[FDIM * FDIM];
    for (int i = threadIdx.x; i < FDIM * FDIM; i += blockDim.x) Ws[i] = W[i];
    __syncthreads();

    int r = blockIdx.x * blockDim.x + threadIdx.x;
    if (r >= n) return;

    unsigned long long acc2[FDIM / 2];       // col pairs {2j, 2j+1}
#pragma unroll
    for (int j = 0; j < FDIM / 2; j++) acc2[j] = 0ull;

    const float4* x4 = (const float4*)(in + (size_t)r * FDIM);
#pragma unroll 4
    for (int k4 = 0; k4 < FDIM / 4; k4++) {
        float4 xv = __ldg(x4 + k4);
        float xs[4] = {xv.x, xv.y, xv.z, xv.w};
#pragma unroll
        for (int kk = 0; kk < 4; kk++) {
            float xk = xs[kk];
            if (LRELU) xk = xk > 0.0f ? xk : 0.01f * xk;
            unsigned long long xk2 = pack2(xk);
            const ulonglong2* Wr = (const ulonglong2*)&Ws[(k4 * 4 + kk) * FDIM];
#pragma unroll
            for (int j = 0; j < FDIM / 4; j++) {
                ulonglong2 w2 = Wr[j];       // cols 4j..4j+3
                acc2[2 * j]     = ffma2(xk2, w2.x, acc2[2 * j]);
                acc2[2 * j + 1] = ffma2(xk2, w2.y, acc2[2 * j + 1]);
            }
        }
    }

    H8* hr = (H8*)(h + (size_t)r * FDIM);
#pragma unroll
    for (int j = 0; j < 8; j++) {
        float2 p0 = unpack2(acc2[4 * j + 0]);
        float2 p1 = unpack2(acc2[4 * j + 1]);
        float2 p2 = unpack2(acc2[4 * j + 2]);
        float2 p3 = unpack2(acc2[4 * j + 3]);
        H8 v;
        v.a = __floats2half2_rn(p0.x, p0.y);
        v.b = __floats2half2_rn(p1.x, p1.y);
        v.c = __floats2half2_rn(p2.x, p2.y);
        v.d = __floats2half2_rn(p3.x, p3.y);
        hr[j] = v;
    }
}

// --- CSR gather: warp per node. lane = eg*8 + c8.
//     eg in 0..3 strides edges by 4; c8 owns 8 fp16 cols (16B).
//     Partials reduced with shfl_xor(8), shfl_xor(16); eg==0 stores.
__device__ __forceinline__ void acc_h8(const H8& v, float nn, float* a) {
    float2 f0 = __half22float2(v.a);
    float2 f1 = __half22float2(v.b);
    float2 f2 = __half22float2(v.c);
    float2 f3 = __half22float2(v.d);
    a[0] = fmaf(f0.x, nn, a[0]); a[1] = fmaf(f0.y, nn, a[1]);
    a[2] = fmaf(f1.x, nn, a[2]); a[3] = fmaf(f1.y, nn, a[3]);
    a[4] = fmaf(f2.x, nn, a[4]); a[5] = fmaf(f2.y, nn, a[5]);
    a[6] = fmaf(f3.x, nn, a[6]); a[7] = fmaf(f3.y, nn, a[7]);
}

__global__ void __launch_bounds__(256)
k_gather(const __half* __restrict__ h, float* __restrict__ out,
         const float* __restrict__ b, int n) {
    int node = blockIdx.x * 8 + (threadIdx.x >> 5);
    if (node >= n) return;
    int lane = threadIdx.x & 31;
    int c8   = lane & 7;
    int eg   = lane >> 3;

    const H8* h8 = (const H8*)h;
    int start = g_row[node];
    int deg   = g_cnt[node];

    float a[8];
#pragma unroll
    for (int i = 0; i < 8; i++) a[i] = 0.0f;

    if (eg == 0) {   // self loop + bias folded into eg0's partial
        float di = g_dinv[node];
        float sn = di * di;
        H8 self = h8[(size_t)node * 8 + c8];
        float2 f0 = __half22float2(self.a), f1 = __half22float2(self.b);
        float2 f2 = __half22float2(self.c), f3 = __half22float2(self.d);
        const float4* bv4 = (const float4*)(b + c8 * 8);
        float4 b0 = __ldg(bv4), b1 = __ldg(bv4 + 1);
        a[0] = fmaf(f0.x, sn, b0.x); a[1] = fmaf(f0.y, sn, b0.y);
        a[2] = fmaf(f1.x, sn, b0.z); a[3] = fmaf(f1.y, sn, b0.w);
        a[4] = fmaf(f2.x, sn, b1.x); a[5] = fmaf(f2.y, sn, b1.y);
        a[6] = fmaf(f3.x, sn, b1.z); a[7] = fmaf(f3.y, sn, b1.w);
    }

    const int2* ed = g_edata + start;
    int e = eg;
    // unroll-2: two independent record+row load pairs in flight
    for (; e + 4 < deg; e += 8) {
        int2 e0 = ed[e];
        int2 e1 = ed[e + 4];
        H8 v0 = h8[(size_t)e0.x * 8 + c8];
        H8 v1 = h8[(size_t)e1.x * 8 + c8];
        acc_h8(v0, __int_as_float(e0.y), a);
        acc_h8(v1, __int_as_float(e1.y), a);
    }
    if (e < deg) {
        int2 e0 = ed[e];
        H8 v0 = h8[(size_t)e0.x * 8 + c8];
        acc_h8(v0, __int_as_float(e0.y), a);
    }

    // reduce across the 4 edge groups (lanes differing in bits 3,4)
#pragma unroll
    for (int i = 0; i < 8; i++) {
        a[i] += __shfl_xor_sync(0xffffffffu, a[i], 8);
        a[i] += __shfl_xor_sync(0xffffffffu, a[i], 16);
    }

    if (eg == 0) {
        float4* o4 = (float4*)(out + (size_t)node * FDIM + c8 * 8);
        o4[0] = make_float4(a[0], a[1], a[2], a[3]);
        o4[1] = make_float4(a[4], a[5], a[6], a[7]);
    }
}

extern "C" void kernel_launch(void* const* d_in, const int* in_sizes, int n_in,
                              void* d_out, int out_size) {
    const float* x  = (const float*)d_in[0];
    const void*  ei = d_in[1];
    const float* W1 = (const float*)d_in[2];
    const float* b1 = (const float*)d_in[3];
    const float* W2 = (const float*)d_in[4];
    const float* b2 = (const float*)d_in[5];
    const float* W3 = (const float*)d_in[6];
    const float* b3 = (const float*)d_in[7];
    float* out = (float*)d_out;

    int n = in_sizes[0] / FDIM;
    long long E = (long long)in_sizes[1] / 2;

    __half* hbuf;
    float* accbuf;
    cudaGetSymbolAddress((void**)&hbuf, g_h);
    cudaGetSymbolAddress((void**)&accbuf, g_acc);

    int nb_n    = (n + 255) / 256;
    int nb_e    = (int)((E + 255) / 256);
    int nb_g    = (n + 127) / 128;
    int nb_scan = (n + 1023) / 1024;
    int nb_ga   = (n + 7) / 8;

    // --- prep: CSR build
    k_detect<<<1, 256>>>((const unsigned int*)ei, 2 * E);
    k_zero2<<<nb_n, 256>>>(n);
    k_deg<<<nb_e, 256>>>(ei, E);
    k_dinv<<<nb_n, 256>>>(n);
    k_scan1<<<nb_scan, 1024>>>(n);
    k_scan2<<<1, 256>>>(nb_scan);
    k_scan3<<<nb_scan, 1024>>>(n);
    k_fill<<<nb_e, 256>>>(ei, E);

    // --- layer 1
    k_gemm<0><<<nb_g, 128>>>(x, W1, hbuf, n);
    k_gather<<<nb_ga, 256>>>(hbuf, accbuf, b1, n);
    // --- layer 2
    k_gemm<1><<<nb_g, 128>>>(accbuf, W2, hbuf, n);
    k_gather<<<nb_ga, 256>>>(hbuf, accbuf, b2, n);
    // --- layer 3
    k_gemm<1><<<nb_g, 128>>>(accbuf, W3, hbuf, n);
    k_gather<<<nb_ga, 256>>>(hbuf, out, b3, n);
}

// round 8
// speedup vs baseline: 1.1311x; 1.1311x over previous
#include <cuda_runtime.h>
#include <cuda_fp16.h>
#include <cstdint>

// ---------------------------------------------------------------------------
// SimpleGCN on B200, round 8:
//   - scan-free CSR: row[i] = atomicAdd(&total, cnt[i]) (disjoint, unordered)
//   - 10 launches; launch #5 is k_gather layer 1 (ncu -s 5 -c 1 captures it)
//   - gather reverted to best-measured R4 layout (fp32 h, 16 thr/node)
//   - GEMM keeps packed fma.rn.f32x2, fp32 epilogue
// ---------------------------------------------------------------------------

#define MAXN (1 << 17)
#define MAXE (1 << 21)
#define FDIM 64

__device__ float g_h[(size_t)MAXN * FDIM];
__device__ float g_acc[(size_t)MAXN * FDIM];
__device__ float g_dinv[MAXN];
__device__ int   g_cnt[MAXN];
__device__ int   g_row[MAXN];
__device__ int   g_cur[MAXN];
__device__ int   g_total;
__device__ int2  g_edata[MAXE];
__device__ int   g_is64;

// --- packed f32x2 helpers ---
__device__ __forceinline__ unsigned long long ffma2(
    unsigned long long a, unsigned long long b, unsigned long long c) {
    unsigned long long d;
    asm("fma.rn.f32x2 %0, %1, %2, %3;" : "=l"(d) : "l"(a), "l"(b), "l"(c));
    return d;
}
__device__ __forceinline__ unsigned long long pack2(float x) {
    unsigned long long p;
    asm("mov.b64 %0, {%1, %1};" : "=l"(p) : "f"(x));
    return p;
}
__device__ __forceinline__ float2 unpack2(unsigned long long p) {
    float lo, hi;
    asm("mov.b64 {%0, %1}, %2;" : "=f"(lo), "=f"(hi) : "l"(p));
    return make_float2(lo, hi);
}

// --- launch 0: detect idx dtype (block 0) + zero counters (all blocks)
__global__ void k_prep0(const unsigned int* __restrict__ w, long long nwords, int n) {
    int i = blockIdx.x * blockDim.x + threadIdx.x;
    if (i < n) { g_cnt[i] = 0; g_cur[i] = 0; }
    if (i == 0) g_total = 0;
    if (blockIdx.x == 0) {
        __shared__ int cnt;
        if (threadIdx.x == 0) cnt = 0;
        __syncthreads();
        int zeros = 0;
        for (long long j = threadIdx.x; j < 2048 && j < nwords; j += blockDim.x)
            if ((j & 1) && w[j] == 0u) zeros++;
        atomicAdd(&cnt, zeros);
        __syncthreads();
        if (threadIdx.x == 0) g_is64 = (cnt > 512) ? 1 : 0;
    }
}

__device__ __forceinline__ int load_idx(const void* e, long long pos) {
    if (g_is64) return (int)((const long long*)e)[pos];
    return ((const int*)e)[pos];
}

// --- launch 1: in-degree histogram
__global__ void k_deg(const void* __restrict__ e, long long E) {
    long long i = (long long)blockIdx.x * blockDim.x + threadIdx.x;
    if (i >= E) return;
    atomicAdd(&g_cnt[load_idx(e, E + i)], 1);
}

// --- launch 2: dinv + unordered CSR range allocation (no scan needed:
//     rows must be disjoint, not sorted)
__global__ void k_dinv_alloc(int n) {
    int i = blockIdx.x * blockDim.x + threadIdx.x;
    if (i >= n) return;
    int c = g_cnt[i];
    g_dinv[i] = rsqrtf((float)(1 + c));   // +1 self loop
    g_row[i] = atomicAdd(&g_total, c);
}

// --- launch 3: CSR fill {src, norm} per edge
__global__ void k_fill(const void* __restrict__ e, long long E) {
    long long i = (long long)blockIdx.x * blockDim.x + threadIdx.x;
    if (i >= E) return;
    int s, d;
    if (g_is64) {
        const long long* p = (const long long*)e;
        s = (int)p[i]; d = (int)p[E + i];
    } else {
        const int* p = (const int*)e;
        s = p[i]; d = p[E + i];
    }
    int pos = g_row[d] + atomicAdd(&g_cur[d], 1);
    g_edata[pos] = make_int2(s, __float_as_int(g_dinv[s] * g_dinv[d]));
}

// --- GEMM: h = act(in) @ W via packed f32x2 FMA (fp32 out)
template <int LRELU>
__global__ void __launch_bounds__(128)
k_gemm(const float* __restrict__ in, const float* __restrict__ W,
       float* __restrict__ h, int n) {
    __shared__ float Ws[FDIM * FDIM];
    for (int i = threadIdx.x; i < FDIM * FDIM; i += blockDim.x) Ws[i] = W[i];
    __syncthreads();

    int r = blockIdx.x * blockDim.x + threadIdx.x;
    if (r >= n) return;

    unsigned long long acc2[FDIM / 2];     // col pairs {2m, 2m+1}
#pragma unroll
    for (int j = 0; j < FDIM / 2; j++) acc2[j] = 0ull;

    const float4* x4 = (const float4*)(in + (size_t)r * FDIM);
#pragma unroll 4
    for (int k4 = 0; k4 < FDIM / 4; k4++) {
        float4 xv = __ldg(x4 + k4);
        float xs[4] = {xv.x, xv.y, xv.z, xv.w};
#pragma unroll
        for (int kk = 0; kk < 4; kk++) {
            float xk = xs[kk];
            if (LRELU) xk = xk > 0.0f ? xk : 0.01f * xk;
            unsigned long long xk2 = pack2(xk);
            const ulonglong2* Wr = (const ulonglong2*)&Ws[(k4 * 4 + kk) * FDIM];
#pragma unroll
            for (int j = 0; j < FDIM / 4; j++) {
                ulonglong2 w2 = Wr[j];     // cols 4j..4j+3
                acc2[2 * j]     = ffma2(xk2, w2.x, acc2[2 * j]);
                acc2[2 * j + 1] = ffma2(xk2, w2.y, acc2[2 * j + 1]);
            }
        }
    }

    float4* hr = (float4*)(h + (size_t)r * FDIM);
#pragma unroll
    for (int j = 0; j < FDIM / 4; j++) {
        float2 lo = unpack2(acc2[2 * j]);
        float2 hi = unpack2(acc2[2 * j + 1]);
        hr[j] = make_float4(lo.x, lo.y, hi.x, hi.y);
    }
}

// --- CSR gather (R4 layout: 16 threads/node, one float4 slab each, unroll-4)
__global__ void __launch_bounds__(256)
k_gather(const float* __restrict__ h, float* __restrict__ out,
         const float* __restrict__ b, int n) {
    int node = blockIdx.x * 16 + (threadIdx.x >> 4);
    if (node >= n) return;
    int c = (threadIdx.x & 15) << 2;

    const float4* h4 = (const float4*)h;
    int start = g_row[node];
    int deg   = g_cnt[node];
    float di  = g_dinv[node];
    float sn  = di * di;

    float4 self = h4[node * 16 + (c >> 2)];
    float4 bv   = __ldg((const float4*)(b + c));
    float4 a;
    a.x = fmaf(self.x, sn, bv.x);
    a.y = fmaf(self.y, sn, bv.y);
    a.z = fmaf(self.z, sn, bv.z);
    a.w = fmaf(self.w, sn, bv.w);

    const int2* ed = g_edata + start;
    int e = 0;
    for (; e + 4 <= deg; e += 4) {
        int2 e0 = ed[e], e1 = ed[e + 1], e2 = ed[e + 2], e3 = ed[e + 3];
        float4 v0 = h4[e0.x * 16 + (c >> 2)];
        float4 v1 = h4[e1.x * 16 + (c >> 2)];
        float4 v2 = h4[e2.x * 16 + (c >> 2)];
        float4 v3 = h4[e3.x * 16 + (c >> 2)];
        float n0 = __int_as_float(e0.y), n1 = __int_as_float(e1.y);
        float n2 = __int_as_float(e2.y), n3 = __int_as_float(e3.y);
        a.x = fmaf(v0.x, n0, a.x); a.y = fmaf(v0.y, n0, a.y);
        a.z = fmaf(v0.z, n0, a.z); a.w = fmaf(v0.w, n0, a.w);
        a.x = fmaf(v1.x, n1, a.x); a.y = fmaf(v1.y, n1, a.y);
        a.z = fmaf(v1.z, n1, a.z); a.w = fmaf(v1.w, n1, a.w);
        a.x = fmaf(v2.x, n2, a.x); a.y = fmaf(v2.y, n2, a.y);
        a.z = fmaf(v2.z, n2, a.z); a.w = fmaf(v2.w, n2, a.w);
        a.x = fmaf(v3.x, n3, a.x); a.y = fmaf(v3.y, n3, a.y);
        a.z = fmaf(v3.z, n3, a.z); a.w = fmaf(v3.w, n3, a.w);
    }
    for (; e < deg; e++) {
        int2 ee = ed[e];
        float4 v = h4[ee.x * 16 + (c >> 2)];
        float nn = __int_as_float(ee.y);
        a.x = fmaf(v.x, nn, a.x); a.y = fmaf(v.y, nn, a.y);
        a.z = fmaf(v.z, nn, a.z); a.w = fmaf(v.w, nn, a.w);
    }

    ((float4*)out)[node * 16 + (c >> 2)] = a;
}

extern "C" void kernel_launch(void* const* d_in, const int* in_sizes, int n_in,
                              void* d_out, int out_size) {
    const float* x  = (const float*)d_in[0];
    const void*  ei = d_in[1];
    const float* W1 = (const float*)d_in[2];
    const float* b1 = (const float*)d_in[3];
    const float* W2 = (const float*)d_in[4];
    const float* b2 = (const float*)d_in[5];
    const float* W3 = (const float*)d_in[6];
    const float* b3 = (const float*)d_in[7];
    float* out = (float*)d_out;

    int n = in_sizes[0] / FDIM;
    long long E = (long long)in_sizes[1] / 2;

    float *hbuf, *accbuf;
    cudaGetSymbolAddress((void**)&hbuf, g_h);
    cudaGetSymbolAddress((void**)&accbuf, g_acc);

    int nb_n  = (n + 255) / 256;
    int nb_e  = (int)((E + 255) / 256);
    int nb_g  = (n + 127) / 128;
    int nb_ga = (n + 15) / 16;

    // launches 0..3: prep (scan-free CSR)
    k_prep0<<<nb_n, 256>>>((const unsigned int*)ei, 2 * E, n);  // 0
    k_deg<<<nb_e, 256>>>(ei, E);                                // 1
    k_dinv_alloc<<<nb_n, 256>>>(n);                             // 2
    k_fill<<<nb_e, 256>>>(ei, E);                               // 3

    // layer 1
    k_gemm<0><<<nb_g, 128>>>(x, W1, hbuf, n);                   // 4
    k_gather<<<nb_ga, 256>>>(hbuf, accbuf, b1, n);              // 5  <- profiled
    // layer 2
    k_gemm<1><<<nb_g, 128>>>(accbuf, W2, hbuf, n);              // 6
    k_gather<<<nb_ga, 256>>>(hbuf, accbuf, b2, n);              // 7
    // layer 3
    k_gemm<1><<<nb_g, 128>>>(accbuf, W3, hbuf, n);              // 8
    k_gather<<<nb_ga, 256>>>(hbuf, out, b3, n);                 // 9
}